// round 4
// baseline (speedup 1.0000x reference)
#include <cuda_runtime.h>

// BambooBase fused Coulomb(Ewald) + D3-CSO dispersion edge kernel.
// R4: 2 edges/thread vectorized (as R3) + occupancy restored via
// __launch_bounds__(256,7) (<=36 regs -> 87.5% occ) and phase-split
// computation (Coulomb stored before dispersion starts) to shrink the
// peak live-register set. Odd-E tail moved to a separate kernel.

#define MAX_ATOMS 200064

__device__ float4 g_atom[MAX_ATOMS];

__global__ __launch_bounds__(256) void pack_atoms_kernel(
    const float* __restrict__ charge,
    const float* __restrict__ c6,
    const float* __restrict__ r0,
    int N)
{
    int i = blockIdx.x * blockDim.x + threadIdx.x;
    if (i >= N) return;
    const float SQRT_ELE = 18.222615f;   // sqrt(332.0637)
    float4 p;
    p.x = charge[i] * SQRT_ELE;
    p.y = sqrtf(c6[i]);
    p.z = 1.25f * r0[i];                 // so 2.5*r0ij = z_r + z_c
    p.w = 0.0f;
    g_atom[i] = p;
}

// ---- Coulomb piece: returns ecoul and cscale (= fcoul / rij^2) ----
__device__ __forceinline__ void coulomb_part(
    float qq, float rij, float rinv, float& ecoul, float& cscale)
{
    const float EWALD_F    = 1.12837917f;
    const float EWALD_P    = 0.3275911f;
    const float A0 = 0.254829592f, A1 = -0.284496736f, A2 = 1.421413741f,
                A3 = -1.453152027f, A4 = 1.061405429f;
    const float COUL_R0    = 2.2f;
    const float INV_R0     = 1.0f / 2.2f;
    const float BETA_OVER_R0 = 18.7f / 2.2f;
    const float INV_BETA   = 1.0f / 18.7f;
    const float G_EWALD    = 0.3f;

    float prefactor = qq * rinv;

    float x  = BETA_OVER_R0 * (rij - COUL_R0);
    float ex = __expf(x);
    float one_p_ex = 1.0f + ex;
    float inv_1pex = 1.0f / one_p_ex;
    float damp = ex * inv_1pex;
    float sp   = __logf(one_p_ex) * INV_BETA;
    float s    = rij * INV_R0 / (1.0f + sp);

    ecoul = prefactor * s;
    float fcoul = prefactor * damp * s * s;

    float grij  = G_EWALD * rij;
    float expm2 = __expf(-grij * grij);
    float t     = 1.0f / (1.0f + EWALD_P * grij);
    float erfc  = t * (A0 + t * (A1 + t * (A2 + t * (A3 + t * A4)))) * expm2;

    ecoul += prefactor * (erfc - 1.0f);
    fcoul += prefactor * (erfc + EWALD_F * grij * expm2 - 1.0f);

    cscale = fcoul * rinv * rinv;
}

// ---- Dispersion piece: returns edisp and dscale (= fdisp / rij) ----
__device__ __forceinline__ void disp_part(
    float c6ij, float zsum, float r2, float rij, float rinv,
    float& edisp, float& dscale)
{
    const float R6_SHIFT = 8303.765625f;   // 4.5^6
    const float INV_CUT6 = 1.0e-6f;

    float r6pow = r2 * r2 * r2;
    float inv_r6 = 1.0f / (r6pow + R6_SHIFT);

    float e   = __expf(rij - zsum);        // rij - 2.5*r0ij
    float inv_1pe = 1.0f / (1.0f + e);
    float cso = 0.85f + 0.82f * inv_1pe;

    float c6_inv_r6 = c6ij * inv_r6;
    edisp = c6ij * INV_CUT6 - c6_inv_r6 * cso;

    float r5 = r2 * r2 * rij;
    float fdisp = -6.0f * c6ij * r5 * inv_r6 * inv_r6 * cso
                  - c6_inv_r6 * (0.82f * e * inv_1pe * inv_1pe);
    dscale = fdisp * rinv;
}

__global__ __launch_bounds__(256, 7) void bamboo_edge_kernel2(
    const int2* __restrict__ row2,
    const int2* __restrict__ col2,
    const float2* __restrict__ dij2,
    float* __restrict__ out,
    int E)
{
    int t = blockIdx.x * blockDim.x + threadIdx.x;
    int nPairs = E >> 1;
    if (t >= nPairs) return;

    int2 rr = row2[t];
    int2 cc = col2[t];
    float2 da = dij2[3*t + 0];
    float2 db = dij2[3*t + 1];
    float2 dc = dij2[3*t + 2];

    float4 pa0 = g_atom[rr.x];
    float4 pb0 = g_atom[cc.x];
    float4 pa1 = g_atom[rr.y];
    float4 pb1 = g_atom[cc.y];

    // edge0: (da.x, da.y, db.x)   edge1: (db.y, dc.x, dc.y)
    float r2_0 = da.x*da.x + da.y*da.y + db.x*db.x;
    float r2_1 = db.y*db.y + dc.x*dc.x + dc.y*dc.y;
    float rinv0 = rsqrtf(r2_0);
    float rinv1 = rsqrtf(r2_1);
    float rij0 = r2_0 * rinv0;
    float rij1 = r2_1 * rinv1;

    float2* out_e  = (float2*)out;
    float2* out_cf = (float2*)(out + (long)E);
    float2* out_ed = (float2*)(out + 4*(long)E);
    float2* out_df = (float2*)(out + 5*(long)E);

    // ---- Phase 1: Coulomb (both edges), store immediately ----
    {
        float e0, cs0, e1, cs1;
        coulomb_part(pa0.x * pb0.x, rij0, rinv0, e0, cs0);
        coulomb_part(pa1.x * pb1.x, rij1, rinv1, e1, cs1);

        out_e[t]      = make_float2(e0, e1);
        out_cf[3*t+0] = make_float2(da.x * cs0, da.y * cs0);
        out_cf[3*t+1] = make_float2(db.x * cs0, db.y * cs1);
        out_cf[3*t+2] = make_float2(dc.x * cs1, dc.y * cs1);
    }

    // ---- Phase 2: Dispersion (both edges), store ----
    {
        float ed0, ds0, ed1, ds1;
        disp_part(pa0.y * pb0.y, pa0.z + pb0.z, r2_0, rij0, rinv0, ed0, ds0);
        disp_part(pa1.y * pb1.y, pa1.z + pb1.z, r2_1, rij1, rinv1, ed1, ds1);

        out_ed[t]     = make_float2(ed0, ed1);
        out_df[3*t+0] = make_float2(da.x * ds0, da.y * ds0);
        out_df[3*t+1] = make_float2(db.x * ds0, db.y * ds1);
        out_df[3*t+2] = make_float2(dc.x * ds1, dc.y * ds1);
    }
}

// Scalar tail for odd E (not expected here: E = 4M).
__global__ void bamboo_edge_tail(
    const int* __restrict__ row,
    const int* __restrict__ col,
    const float* __restrict__ dij,
    float* __restrict__ out,
    int E)
{
    int i = E - 1;
    float4 pa = g_atom[row[i]];
    float4 pb = g_atom[col[i]];
    float dx = dij[3*i], dy = dij[3*i+1], dz = dij[3*i+2];
    float r2 = dx*dx + dy*dy + dz*dz;
    float rinv = rsqrtf(r2);
    float rij = r2 * rinv;
    float e, cs, ed, ds;
    coulomb_part(pa.x * pb.x, rij, rinv, e, cs);
    disp_part(pa.y * pb.y, pa.z + pb.z, r2, rij, rinv, ed, ds);
    long Eo = (long)E;
    out[i] = e;
    out[Eo + 3L*i + 0] = dx * cs;
    out[Eo + 3L*i + 1] = dy * cs;
    out[Eo + 3L*i + 2] = dz * cs;
    out[4*Eo + i] = ed;
    out[5*Eo + 3L*i + 0] = dx * ds;
    out[5*Eo + 3L*i + 1] = dy * ds;
    out[5*Eo + 3L*i + 2] = dz * ds;
}

extern "C" void kernel_launch(void* const* d_in, const int* in_sizes, int n_in,
                              void* d_out, int out_size)
{
    const int*   row    = (const int*)d_in[0];
    const int*   col    = (const int*)d_in[1];
    const float* dij    = (const float*)d_in[2];
    const float* charge = (const float*)d_in[3];
    const float* c6     = (const float*)d_in[4];
    const float* r0     = (const float*)d_in[5];
    float* out = (float*)d_out;

    int E = in_sizes[0];
    int N = in_sizes[3];

    int threads = 256;
    pack_atoms_kernel<<<(N + threads - 1) / threads, threads>>>(charge, c6, r0, N);

    int nPairs = E >> 1;
    if (nPairs > 0) {
        bamboo_edge_kernel2<<<(nPairs + threads - 1) / threads, threads>>>(
            (const int2*)row, (const int2*)col, (const float2*)dij, out, E);
    }
    if (E & 1) {
        bamboo_edge_tail<<<1, 1>>>(row, col, dij, out, E);
    }
}

// round 5
// speedup vs baseline: 1.2748x; 1.2748x over previous
#include <cuda_runtime.h>

// BambooBase fused Coulomb(Ewald) + D3-CSO dispersion edge kernel.
// R5: back to the R2 structure (1 edge/thread scalar — proven best memory
// behavior), with all 5 fp32 divisions replaced by MUFU.RCP approximations
// (__fdividef) to cut ~40 instr and ~100 serial cycles per edge, plus a
// vectorized pack prologue.

#define MAX_ATOMS 200064

__device__ float4 g_atom[MAX_ATOMS];

__device__ __forceinline__ float frcp(float x) { return __fdividef(1.0f, x); }

__global__ __launch_bounds__(256) void pack_atoms_kernel(
    const float* __restrict__ charge,
    const float* __restrict__ c6,
    const float* __restrict__ r0,
    int N)
{
    const float SQRT_ELE = 18.222615f;   // sqrt(332.0637)
    int t = blockIdx.x * blockDim.x + threadIdx.x;
    int base = 4 * t;
    if (base + 3 < N) {
        float4 q  = *(const float4*)(charge + base);
        float4 cc = *(const float4*)(c6 + base);
        float4 rr = *(const float4*)(r0 + base);
        g_atom[base + 0] = make_float4(q.x * SQRT_ELE, sqrtf(cc.x), 1.25f * rr.x, 0.f);
        g_atom[base + 1] = make_float4(q.y * SQRT_ELE, sqrtf(cc.y), 1.25f * rr.y, 0.f);
        g_atom[base + 2] = make_float4(q.z * SQRT_ELE, sqrtf(cc.z), 1.25f * rr.z, 0.f);
        g_atom[base + 3] = make_float4(q.w * SQRT_ELE, sqrtf(cc.w), 1.25f * rr.w, 0.f);
    } else {
        for (int i = base; i < N; ++i) {
            g_atom[i] = make_float4(charge[i] * SQRT_ELE, sqrtf(c6[i]), 1.25f * r0[i], 0.f);
        }
    }
}

__global__ __launch_bounds__(256) void bamboo_edge_kernel(
    const int* __restrict__ row,
    const int* __restrict__ col,
    const float* __restrict__ dij,
    float* __restrict__ out,
    int E)
{
    int i = blockIdx.x * blockDim.x + threadIdx.x;
    if (i >= E) return;

    const float EWALD_F    = 1.12837917f;
    const float EWALD_P    = 0.3275911f;
    const float A0 = 0.254829592f, A1 = -0.284496736f, A2 = 1.421413741f,
                A3 = -1.453152027f, A4 = 1.061405429f;
    const float COUL_R0    = 2.2f;
    const float INV_R0     = 1.0f / 2.2f;
    const float BETA_OVER_R0 = 18.7f / 2.2f;   // 8.5
    const float INV_BETA   = 1.0f / 18.7f;
    const float G_EWALD    = 0.3f;
    const float R6_SHIFT   = 8303.765625f;      // 4.5^6
    const float INV_CUT6   = 1.0e-6f;           // 1/10^6

    int r = row[i];
    int c = col[i];

    float dx = dij[3*i + 0];
    float dy = dij[3*i + 1];
    float dz = dij[3*i + 2];

    float4 pa = g_atom[r];
    float4 pb = g_atom[c];

    float r2   = dx*dx + dy*dy + dz*dz;
    float rinv = rsqrtf(r2);
    float rij  = r2 * rinv;
    float rinv2 = rinv * rinv;

    // ---- Coulomb ----
    float prefactor = pa.x * pb.x * rinv;      // ELE folded into charges

    float x  = BETA_OVER_R0 * (rij - COUL_R0);
    float ex = __expf(x);
    float one_p_ex = 1.0f + ex;
    float inv_1pex = frcp(one_p_ex);
    float damp = ex * inv_1pex;                        // sigmoid(x)
    float sp   = __logf(one_p_ex) * INV_BETA;          // softplus
    float s    = rij * INV_R0 * frcp(1.0f + sp);

    float ecoul = prefactor * s;
    float fcoul = prefactor * damp * s * s;

    float grij  = G_EWALD * rij;
    float expm2 = __expf(-grij * grij);
    float t     = frcp(1.0f + EWALD_P * grij);
    float erfc  = t * (A0 + t * (A1 + t * (A2 + t * (A3 + t * A4)))) * expm2;

    ecoul += prefactor * (erfc - 1.0f);
    fcoul += prefactor * (erfc + EWALD_F * grij * expm2 - 1.0f);

    float cscale = fcoul * rinv2;
    float cfx = dx * cscale;
    float cfy = dy * cscale;
    float cfz = dz * cscale;

    // ---- Dispersion (D3-CSO) ----
    float c6ij = pa.y * pb.y;                   // sqrt(c6r*c6c)

    float r6pow = r2 * r2 * r2;
    float inv_r6 = frcp(r6pow + R6_SHIFT);

    float e   = __expf(rij - (pa.z + pb.z));    // rij - 2.5*r0ij
    float inv_1pe = frcp(1.0f + e);
    float cso = 0.85f + 0.82f * inv_1pe;

    float c6_inv_r6 = c6ij * inv_r6;
    float edisp = -c6_inv_r6 * cso;

    float r5 = r2 * r2 * rij;
    float fdisp = -6.0f * c6ij * r5 * inv_r6 * inv_r6 * cso
                  - c6_inv_r6 * (0.82f * e * inv_1pe * inv_1pe);

    float dscale = fdisp * rinv;
    float dfx = dx * dscale;
    float dfy = dy * dscale;
    float dfz = dz * dscale;

    edisp += c6ij * INV_CUT6;

    // ---- stores ----
    long Eo = (long)E;
    out[i] = ecoul;
    out[Eo + 3*(long)i + 0] = cfx;
    out[Eo + 3*(long)i + 1] = cfy;
    out[Eo + 3*(long)i + 2] = cfz;
    out[4*Eo + i] = edisp;
    out[5*Eo + 3*(long)i + 0] = dfx;
    out[5*Eo + 3*(long)i + 1] = dfy;
    out[5*Eo + 3*(long)i + 2] = dfz;
}

extern "C" void kernel_launch(void* const* d_in, const int* in_sizes, int n_in,
                              void* d_out, int out_size)
{
    const int*   row    = (const int*)d_in[0];
    const int*   col    = (const int*)d_in[1];
    const float* dij    = (const float*)d_in[2];
    const float* charge = (const float*)d_in[3];
    const float* c6     = (const float*)d_in[4];
    const float* r0     = (const float*)d_in[5];
    float* out = (float*)d_out;

    int E = in_sizes[0];
    int N = in_sizes[3];

    int threads = 256;
    int packThreads = (N + 3) / 4;
    pack_atoms_kernel<<<(packThreads + threads - 1) / threads, threads>>>(charge, c6, r0, N);
    bamboo_edge_kernel<<<(E + threads - 1) / threads, threads>>>(row, col, dij, out, E);
}